// round 8
// baseline (speedup 1.0000x reference)
#include <cuda_runtime.h>

typedef unsigned long long ull;
#define XST 132   // Xs row stride
#define HST 132   // hq_s / hd_s row stride

// ---- f32x2 packed helpers ----
__device__ __forceinline__ ull pack2(float x, float y) {
    ull r; asm("mov.b64 %0, {%1,%2};" : "=l"(r) : "f"(x), "f"(y)); return r;
}
__device__ __forceinline__ void unpack2(ull v, float& x, float& y) {
    asm("mov.b64 {%0,%1}, %2;" : "=f"(x), "=f"(y) : "l"(v));
}
__device__ __forceinline__ ull fma2(ull a, ull b, ull c) {
    ull d; asm("fma.rn.f32x2 %0, %1, %2, %3;" : "=l"(d) : "l"(a), "l"(b), "l"(c)); return d;
}
__device__ __forceinline__ ull add2(ull a, ull b) {
    ull d; asm("add.rn.f32x2 %0, %1, %2;" : "=l"(d) : "l"(a), "l"(b)); return d;
}

// Mask dtype auto-detect: 0 = int32, 1 = uint8, 2 = float32
__device__ __forceinline__ bool mask_at(const void* p, int i, int mode) {
    if (mode == 0) return ((const int*)p)[i] != 0;
    if (mode == 2) return ((const float*)p)[i] != 0.0f;
    return ((const unsigned char*)p)[i] != 0;
}

// ============================================================================
// grid = 256 = (batch, n-half, m-half). 256 threads, 2 blocks/SM (~86KB smem).
// X bulk-staged in smem; W1 staged in [64][128] d-chunks (4 stages total).
// Proj mapping: warp owns a 32-h slice; thread = 1 row x 16 h.
// ============================================================================
__global__ void __launch_bounds__(256, 2)
fused_kernel(const float* __restrict__ query, const float* __restrict__ doc,
             const void* __restrict__ qmask, const void* __restrict__ dmask,
             const float* __restrict__ W1, const float* __restrict__ b1,
             const float* __restrict__ W2g, const float* __restrict__ b2g,
             float* __restrict__ out)
{
    extern __shared__ float sm[];
    float* Ws   = sm;                   // [64][128]  W1 d-chunk
    float* Xs   = Ws + 64 * 128;        // [32][XST]  staged X rows
    float* hq_s = Xs + 32 * XST;        // [32][HST]
    float* hd_s = hq_s + 32 * HST;      // [32][HST]
    float* w2_s = hd_s + 32 * HST;      // [3][128]
    float* b1s  = w2_s + 384;           // [128]
    int* nlist  = (int*)(b1s + 128);    // 34
    int* mlist  = nlist + 34;           // 34
    int* meta   = mlist + 34;           // [0]=notInt [1]=notF32 [2]=nvh [3]=mvh

    const int tid  = threadIdx.x;
    const int lane = tid & 31;
    const int wid  = tid >> 5;
    const int b    = blockIdx.x >> 2;
    const int nh   = (blockIdx.x >> 1) & 1;
    const int mh   = blockIdx.x & 1;

    if (tid < 4) meta[tid] = 0;
    __syncthreads();

    // ---- mask dtype detection + zero-fill own 32x32 output window
    {
        const unsigned* qw = (const unsigned*)qmask;
        int notInt = 0, notF32 = 0;
        for (int i = tid; i < 512; i += 256) {
            unsigned w = qw[i];
            notInt |= (w > 1u) ? 1 : 0;
            notF32 |= (w != 0u && w != 0x3F800000u) ? 1 : 0;
        }
        if (notInt) meta[0] = 1;
        if (notF32) meta[1] = 1;
    }
    float* obase = out + (size_t)((b * 64 + nh * 32) * 64 + mh * 32) * 3;
    {
        float4 z = make_float4(0.f, 0.f, 0.f, 0.f);
        for (int i = tid; i < 768; i += 256) {      // 32 rows x 24 float4
            int r = i / 24, c = i - r * 24;
            ((float4*)(obase + r * 192))[c] = z;
        }
    }
    __syncthreads();
    const int mode = (meta[0] == 0) ? 0 : ((meta[1] == 0) ? 2 : 1);

    // ---- region A: ballots / W2 transpose / b1, then all stage Wq chunk0
    if (wid == 0) {
        bool v = mask_at(qmask, b * 64 + nh * 32 + lane, mode);
        unsigned mm = __ballot_sync(0xFFFFFFFFu, v);
        unsigned lt = (1u << lane) - 1u;
        if (v) nlist[__popc(mm & lt)] = lane;
        if (lane == 0) {
            int c = __popc(mm);
            meta[2] = c;
            if (c & 1) nlist[c] = 31 - __clz(mm);   // pad dup of last valid
        }
    } else if (wid == 1) {
        bool v = mask_at(dmask, b * 64 + mh * 32 + lane, mode);
        unsigned mm = __ballot_sync(0xFFFFFFFFu, v);
        unsigned lt = (1u << lane) - 1u;
        if (v) mlist[__popc(mm & lt)] = lane;
        if (lane == 0) {
            int c = __popc(mm);
            meta[3] = c;
            if (c & 1) mlist[c] = 31 - __clz(mm);
        }
    } else if (wid == 2 || wid == 3) {
        for (int i = tid - 64; i < 384; i += 64) {  // W2 (128,3) -> [o][h]
            int h = i / 3, o = i - h * 3;
            w2_s[o * 128 + h] = W2g[i];
        }
    } else if (wid == 4) {
        for (int i = lane; i < 128; i += 32) b1s[i] = b1[i];
    }
    // stage Wq chunk 0 (all threads): W1 rows [0,64)
    for (int i = tid; i < 2048; i += 256)
        *(float4*)(Ws + (i >> 5) * 128 + (i & 31) * 4) = ((const float4*)W1)[i];
    __syncthreads();

    const int nvh = meta[2], mvh = meta[3];
    const int nvhp = (nvh + 1) & ~1;
    const int mvhp = (mvh + 1) & ~1;

    // proj thread mapping: warp h-slice; thread = 1 row x 16 h
    const int prow = ((wid >> 2) << 4) + (lane & 15);   // 0..31
    const int h0   = ((wid & 3) << 5) + ((lane >> 4) << 4);

    // ---- stage compacted Xq rows
    const float* Xq = query + (size_t)b * 8192;
    for (int i = tid; i < nvhp * 32; i += 256) {
        int r = i >> 5, seg = i & 31;
        *(float4*)(Xs + r * XST + seg * 4) =
            ((const float4*)(Xq + (b * 0 + nh * 32 + nlist[r]) * 128))[seg];
    }
    __syncthreads();

    ull acc[8];
#pragma unroll
    for (int j = 0; j < 8; j++) acc[j] = 0ull;

#define ACCUM_CHUNK(dc) do {                                                 \
        const float* xb = Xs + prow * XST + (dc) * 64;                       \
        const float* wb = Ws + h0;                                           \
        _Pragma("unroll 4")                                                  \
        for (int dl = 0; dl < 64; dl++) {                                    \
            float x = xb[dl];                                                \
            ull px = pack2(x, x);                                            \
            const ulonglong2* wr = (const ulonglong2*)(wb + dl * 128);       \
            ulonglong2 wa = wr[0], wb2 = wr[1], wc = wr[2], wd = wr[3];      \
            acc[0] = fma2(px, wa.x,  acc[0]);                                \
            acc[1] = fma2(px, wa.y,  acc[1]);                                \
            acc[2] = fma2(px, wb2.x, acc[2]);                                \
            acc[3] = fma2(px, wb2.y, acc[3]);                                \
            acc[4] = fma2(px, wc.x,  acc[4]);                                \
            acc[5] = fma2(px, wc.y,  acc[5]);                                \
            acc[6] = fma2(px, wd.x,  acc[6]);                                \
            acc[7] = fma2(px, wd.y,  acc[7]);                                \
        }                                                                    \
    } while (0)

    // ---- hq: chunk 0, restage W, chunk 1
    if (prow < nvhp) ACCUM_CHUNK(0);
    __syncthreads();
    for (int i = tid; i < 2048; i += 256)   // Wq chunk 1: W1 rows [64,128)
        *(float4*)(Ws + (i >> 5) * 128 + (i & 31) * 4) =
            ((const float4*)(W1 + 8192))[i];
    __syncthreads();
    if (prow < nvhp) {
        ACCUM_CHUNK(1);
        float v[16];
#pragma unroll
        for (int j = 0; j < 8; j++) unpack2(acc[j], v[2 * j], v[2 * j + 1]);
#pragma unroll
        for (int k = 0; k < 16; k++) v[k] += b1s[h0 + k];
        float* go = hq_s + prow * HST + h0;
#pragma unroll
        for (int q = 0; q < 4; q++)
            *(float4*)(go + q * 4) =
                make_float4(v[4 * q], v[4 * q + 1], v[4 * q + 2], v[4 * q + 3]);
    }
    __syncthreads();

    // ---- stage Wd chunk 0 + compacted Xd rows
    for (int i = tid; i < 2048; i += 256)   // W1 rows [128,192)
        *(float4*)(Ws + (i >> 5) * 128 + (i & 31) * 4) =
            ((const float4*)(W1 + 16384))[i];
    const float* Xd = doc + (size_t)b * 8192;
    for (int i = tid; i < mvhp * 32; i += 256) {
        int r = i >> 5, seg = i & 31;
        *(float4*)(Xs + r * XST + seg * 4) =
            ((const float4*)(Xd + (mh * 32 + mlist[r]) * 128))[seg];
    }
    __syncthreads();

#pragma unroll
    for (int j = 0; j < 8; j++) acc[j] = 0ull;

    if (prow < mvhp) ACCUM_CHUNK(0);
    __syncthreads();
    for (int i = tid; i < 2048; i += 256)   // W1 rows [192,256)
        *(float4*)(Ws + (i >> 5) * 128 + (i & 31) * 4) =
            ((const float4*)(W1 + 24576))[i];
    __syncthreads();
    if (prow < mvhp) {
        ACCUM_CHUNK(1);
        float v[16];
#pragma unroll
        for (int j = 0; j < 8; j++) unpack2(acc[j], v[2 * j], v[2 * j + 1]);
        float* go = hd_s + prow * HST + h0;
#pragma unroll
        for (int q = 0; q < 4; q++)
            *(float4*)(go + q * 4) =
                make_float4(v[4 * q], v[4 * q + 1], v[4 * q + 2], v[4 * q + 3]);
    }
    __syncthreads();
#undef ACCUM_CHUNK

    // ---- pairwise: <=256 2x2 tiles, rows paired (i, i+count/2)
    const int nt = nvhp >> 1, mt = mvhp >> 1;
    const int total = nt * mt;
    const float b2_0 = b2g[0], b2_1 = b2g[1], b2_2 = b2g[2];

    for (int t = tid; t < total; t += 256) {
        const int ni = t / mt;
        const int mi = t - ni * mt;
        const float* pa0 = hq_s + ni * HST;
        const float* pa1 = hq_s + (ni + nt) * HST;
        const float* pd0 = hd_s + mi * HST;
        const float* pd1 = hd_s + (mi + mt) * HST;

        ull acc2[4][3];
#pragma unroll
        for (int c = 0; c < 4; c++)
#pragma unroll
            for (int o = 0; o < 3; o++) acc2[c][o] = 0ull;

#define COMBO(c, Alo, Ahi, Dlo, Dhi) do {                                   \
            ull tlo = add2((Alo), (Dlo));                                    \
            ull thi = add2((Ahi), (Dhi));                                    \
            float f0, f1, f2, f3;                                            \
            unpack2(tlo, f0, f1); unpack2(thi, f2, f3);                      \
            f0 = fmaxf(f0, 0.f); f1 = fmaxf(f1, 0.f);                        \
            f2 = fmaxf(f2, 0.f); f3 = fmaxf(f3, 0.f);                        \
            tlo = pack2(f0, f1); thi = pack2(f2, f3);                        \
            acc2[c][0] = fma2(tlo, w0.x, acc2[c][0]);                        \
            acc2[c][0] = fma2(thi, w0.y, acc2[c][0]);                        \
            acc2[c][1] = fma2(tlo, w1.x, acc2[c][1]);                        \
            acc2[c][1] = fma2(thi, w1.y, acc2[c][1]);                        \
            acc2[c][2] = fma2(tlo, w2v.x, acc2[c][2]);                       \
            acc2[c][2] = fma2(thi, w2v.y, acc2[c][2]);                       \
        } while (0)

#pragma unroll 4
        for (int h = 0; h < 128; h += 4) {
            ulonglong2 A0 = *(const ulonglong2*)(pa0 + h);
            ulonglong2 A1 = *(const ulonglong2*)(pa1 + h);
            ulonglong2 D0 = *(const ulonglong2*)(pd0 + h);
            ulonglong2 D1 = *(const ulonglong2*)(pd1 + h);
            ulonglong2 w0  = *(const ulonglong2*)(w2_s + h);
            ulonglong2 w1  = *(const ulonglong2*)(w2_s + 128 + h);
            ulonglong2 w2v = *(const ulonglong2*)(w2_s + 256 + h);
            COMBO(0, A0.x, A0.y, D0.x, D0.y);
            COMBO(1, A0.x, A0.y, D1.x, D1.y);
            COMBO(2, A1.x, A1.y, D0.x, D0.y);
            COMBO(3, A1.x, A1.y, D1.x, D1.y);
        }
#undef COMBO

        const int gn0 = nlist[ni], gn1 = nlist[ni + nt];
        const int gm0 = mlist[mi], gm1 = mlist[mi + mt];

#define WRITE(c, gn, gm) do {                                               \
            float lo, hi, s0, s1, s2;                                        \
            unpack2(acc2[c][0], lo, hi); s0 = lo + hi + b2_0;                \
            unpack2(acc2[c][1], lo, hi); s1 = lo + hi + b2_1;                \
            unpack2(acc2[c][2], lo, hi); s2 = lo + hi + b2_2;                \
            float* po = obase + (gn) * 192 + (gm) * 3;                       \
            po[0] = s0; po[1] = s1; po[2] = s2;                              \
        } while (0)

        WRITE(0, gn0, gm0);
        WRITE(1, gn0, gm1);
        WRITE(2, gn1, gm0);
        WRITE(3, gn1, gm1);
#undef WRITE
    }
}

// ============================================================================
extern "C" void kernel_launch(void* const* d_in, const int* in_sizes, int n_in,
                              void* d_out, int out_size)
{
    const float* query = (const float*)d_in[0];
    const float* doc   = (const float*)d_in[1];
    const void*  qmask = d_in[2];
    const void*  dmask = d_in[3];
    const float* W1    = (const float*)d_in[4];
    const float* b1    = (const float*)d_in[5];
    const float* W2    = (const float*)d_in[6];
    const float* b2    = (const float*)d_in[7];
    float* out = (float*)d_out;

    const int smem = (64 * 128 + 32 * XST + 32 * HST + 32 * HST + 384 + 128)
                         * (int)sizeof(float)
                     + (34 + 34 + 4) * (int)sizeof(int);   // ~86 KB

    cudaFuncSetAttribute(fused_kernel,
                         cudaFuncAttributeMaxDynamicSharedMemorySize, smem);

    fused_kernel<<<256, 256, smem>>>(query, doc, qmask, dmask, W1, b1, W2, b2, out);
}